// round 1
// baseline (speedup 1.0000x reference)
#include <cuda_runtime.h>

#define NN 200000
#define EE 200000

__device__ int g_inv[NN];

__global__ void k_init_inv() {
    int i = blockIdx.x * blockDim.x + threadIdx.x;
    if (i < NN) g_inv[i] = -1;
}

__global__ void k_scatter(const int* __restrict__ dst) {
    int e = blockIdx.x * blockDim.x + threadIdx.x;
    if (e < EE) {
        unsigned d = (unsigned)dst[e];
        if (d < NN) g_inv[d] = e;
    }
}

__device__ __forceinline__ float sigf(float x) {
    return __fdividef(1.0f, 1.0f + __expf(-x));
}
__device__ __forceinline__ float tanh_fast(float x) {
    return 2.0f * __fdividef(1.0f, 1.0f + __expf(-2.0f * x)) - 1.0f;
}

constexpr int TILE = 16;

// shared-memory layout (float offsets)
constexpr int O_WIHN = 0;                 // 384*21 (i,g,o rows only; f gate dead)
constexpr int O_BN   = O_WIHN + 384*21;   // 384
constexpr int O_WIHE = O_BN   + 384;      // 384*2
constexpr int O_BE   = O_WIHE + 768;      // 384
constexpr int O_WNM  = O_BE   + 384;      // 21*257 (padded stride)
constexpr int O_BNM  = O_WNM  + 21*257;   // 21 (+pad)
constexpr int O_WFC  = O_BNM  + 24;       // 4*129 (padded)
constexpr int O_BFC  = O_WFC  + 516;      // 4
constexpr int O_XN   = O_BFC  + 4;        // 16*21
constexpr int O_XE   = O_XN   + 336;      // 16*2
constexpr int O_HN1  = O_XE   + 32;       // 16*129 (padded)
constexpr int O_MAIL = O_HN1  + 2064;     // 16*129
constexpr int O_XN1  = O_MAIL + 2064;     // 16*21
constexpr int O_HN2  = O_XN1  + 336;      // 16*129
constexpr int O_INV  = O_HN2  + 2064;     // 16 ints
constexpr int SMEM_FLOATS = O_INV + 16;   // ~89.8 KB

// node LSTM (zero state): x[16][21] -> h[16][129-padded]
// thread = (k = tid&127, half = tid>>7), each thread: 8 nodes at fixed k.
// Within a warp 'half' is constant -> x loads are broadcast; W loads stride 21 (odd) -> conflict-free.
__device__ __forceinline__ void lstm_n(const float* __restrict__ sm,
                                       float* __restrict__ out_h,
                                       const float* __restrict__ s_x,
                                       int tid) {
    int k = tid & 127;
    int half = tid >> 7;
    float ai[8], ag[8], ao[8];
#pragma unroll
    for (int m = 0; m < 8; m++) { ai[m] = 0.f; ag[m] = 0.f; ao[m] = 0.f; }
    const float* wi = sm + O_WIHN + k * 21;
    const float* wg = sm + O_WIHN + (128 + k) * 21;
    const float* wo = sm + O_WIHN + (256 + k) * 21;
#pragma unroll
    for (int j = 0; j < 21; j++) {
        float wiv = wi[j], wgv = wg[j], wov = wo[j];
#pragma unroll
        for (int m = 0; m < 8; m++) {
            float x = s_x[(half + 2 * m) * 21 + j];
            ai[m] = fmaf(x, wiv, ai[m]);
            ag[m] = fmaf(x, wgv, ag[m]);
            ao[m] = fmaf(x, wov, ao[m]);
        }
    }
    float bi = sm[O_BN + k], bg = sm[O_BN + 128 + k], bo = sm[O_BN + 256 + k];
#pragma unroll
    for (int m = 0; m < 8; m++) {
        int n = half + 2 * m;
        float c = sigf(ai[m] + bi) * tanh_fast(ag[m] + bg);
        float h = sigf(ao[m] + bo) * tanh_fast(c);
        out_h[n * 129 + k] = h;
    }
}

__global__ void __launch_bounds__(256) k_main(
    const float* __restrict__ node_feat,
    const float* __restrict__ edge_feat,
    const float* __restrict__ W_ih_n, const float* __restrict__ b_ih_n, const float* __restrict__ b_hh_n,
    const float* __restrict__ W_ih_e, const float* __restrict__ b_ih_e, const float* __restrict__ b_hh_e,
    const float* __restrict__ W_nmpn, const float* __restrict__ b_nmpn,
    const float* __restrict__ W_fc, const float* __restrict__ b_fc,
    float* __restrict__ out) {
    extern __shared__ float sm[];
    int tid = threadIdx.x;

    // ---- stage weights into shared (once per block) ----
    for (int idx = tid; idx < 384 * 21; idx += 256) {
        int q = idx / 21, j = idx % 21;
        int srow = q < 128 ? q : q + 128;   // skip dead f-gate rows [128,256)
        sm[O_WIHN + idx] = W_ih_n[srow * 21 + j];
    }
    for (int q = tid; q < 384; q += 256) {
        int srow = q < 128 ? q : q + 128;
        sm[O_BN + q] = b_ih_n[srow] + b_hh_n[srow];
        sm[O_BE + q] = b_ih_e[srow] + b_hh_e[srow];
        sm[O_WIHE + 2 * q]     = W_ih_e[srow * 2];
        sm[O_WIHE + 2 * q + 1] = W_ih_e[srow * 2 + 1];
    }
    for (int idx = tid; idx < 21 * 256; idx += 256) {
        int c = idx >> 8, j = idx & 255;
        sm[O_WNM + c * 257 + j] = W_nmpn[idx];
    }
    if (tid < 21) sm[O_BNM + tid] = b_nmpn[tid];
    for (int idx = tid; idx < 512; idx += 256) {
        int c = idx >> 7, j = idx & 127;
        sm[O_WFC + c * 129 + j] = W_fc[idx];
    }
    if (tid < 4) sm[O_BFC + tid] = b_fc[tid];
    __syncthreads();

    int* s_inv = (int*)(sm + O_INV);
    const int numTiles = NN / TILE;

    for (int tile = blockIdx.x; tile < numTiles; tile += gridDim.x) {
        int base = tile * TILE;

        // ---- load tile inputs ----
        if (tid < TILE) {
            int e = g_inv[base + tid];
            s_inv[tid] = e;
            float x0 = 0.f, x1 = 0.f;
            if (e >= 0) { x0 = edge_feat[2 * e]; x1 = edge_feat[2 * e + 1]; }
            sm[O_XE + 2 * tid] = x0;
            sm[O_XE + 2 * tid + 1] = x1;
        }
        for (int p = tid; p < TILE * 21; p += 256)
            sm[O_XN + p] = node_feat[base * 21 + p];
        __syncthreads();

        // ---- stage 1: h_n1 = lstm(xn0) ----
        lstm_n(sm, sm + O_HN1, sm + O_XN, tid);

        // ---- stage 2: mail = scatter(h_e = lstm(xe0)) (dst-inverse) ----
        {
            int k = tid & 127, half = tid >> 7;
            float wi0 = sm[O_WIHE + 2 * k],           wi1 = sm[O_WIHE + 2 * k + 1];
            float wg0 = sm[O_WIHE + 2 * (128 + k)],   wg1 = sm[O_WIHE + 2 * (128 + k) + 1];
            float wo0 = sm[O_WIHE + 2 * (256 + k)],   wo1 = sm[O_WIHE + 2 * (256 + k) + 1];
            float bi = sm[O_BE + k], bg = sm[O_BE + 128 + k], bo = sm[O_BE + 256 + k];
#pragma unroll
            for (int m = 0; m < 8; m++) {
                int n = half + 2 * m;
                float x0 = sm[O_XE + 2 * n], x1 = sm[O_XE + 2 * n + 1];
                float gi = fmaf(x1, wi1, fmaf(x0, wi0, bi));
                float gg = fmaf(x1, wg1, fmaf(x0, wg0, bg));
                float go = fmaf(x1, wo1, fmaf(x0, wo0, bo));
                float c = sigf(gi) * tanh_fast(gg);
                float h = sigf(go) * tanh_fast(c);
                sm[O_MAIL + n * 129 + k] = (s_inv[n] >= 0) ? h : 0.f;
            }
        }
        __syncthreads();

        // ---- stage 3: xn1 = sigmoid([mail, h_n1] @ W_nmpn.T + b) ----
        for (int p = tid; p < TILE * 21; p += 256) {
            int n = p / 21, c = p % 21;
            const float* wm = sm + O_WNM + c * 257;
            const float* dm = sm + O_MAIL + n * 129;
            const float* dh = sm + O_HN1 + n * 129;
            float acc = sm[O_BNM + c];
#pragma unroll 8
            for (int j = 0; j < 128; j++) acc = fmaf(dm[j], wm[j], acc);
#pragma unroll 8
            for (int j = 0; j < 128; j++) acc = fmaf(dh[j], wm[128 + j], acc);
            sm[O_XN1 + p] = sigf(acc);
        }
        __syncthreads();

        // ---- stage 4/5: h_n2 = lstm(xn1) ----
        lstm_n(sm, sm + O_HN2, sm + O_XN1, tid);
        __syncthreads();

        // ---- stage 6: logits + log_softmax (4-lane shuffle groups) ----
        if (tid < 64) {
            int n = tid >> 2, cls = tid & 3;
            const float* w = sm + O_WFC + cls * 129;
            const float* h = sm + O_HN2 + n * 129;
            float acc = sm[O_BFC + cls];
#pragma unroll 8
            for (int j = 0; j < 128; j++) acc = fmaf(h[j], w[j], acc);
            float mx = acc;
            mx = fmaxf(mx, __shfl_xor_sync(0xFFFFFFFF, mx, 1));
            mx = fmaxf(mx, __shfl_xor_sync(0xFFFFFFFF, mx, 2));
            float ev = __expf(acc - mx);
            float s = ev;
            s += __shfl_xor_sync(0xFFFFFFFF, s, 1);
            s += __shfl_xor_sync(0xFFFFFFFF, s, 2);
            out[(base + n) * 4 + cls] = acc - mx - __logf(s);
        }
        __syncthreads();
    }
}

extern "C" void kernel_launch(void* const* d_in, const int* in_sizes, int n_in,
                              void* d_out, int out_size) {
    const float* node_feat = (const float*)d_in[0];
    const float* edge_feat = (const float*)d_in[1];
    const int*   dst       = (const int*)d_in[3];
    const float* W_ih_n    = (const float*)d_in[4];
    const float* b_ih_n    = (const float*)d_in[6];
    const float* b_hh_n    = (const float*)d_in[7];
    const float* W_ih_e    = (const float*)d_in[8];
    const float* b_ih_e    = (const float*)d_in[10];
    const float* b_hh_e    = (const float*)d_in[11];
    const float* W_nmpn    = (const float*)d_in[12];
    const float* b_nmpn    = (const float*)d_in[13];
    const float* W_fc      = (const float*)d_in[16];
    const float* b_fc      = (const float*)d_in[17];
    float* out = (float*)d_out;

    cudaFuncSetAttribute(k_main, cudaFuncAttributeMaxDynamicSharedMemorySize,
                         SMEM_FLOATS * (int)sizeof(float));

    k_init_inv<<<(NN + 255) / 256, 256>>>();
    k_scatter<<<(EE + 255) / 256, 256>>>(dst);
    k_main<<<592, 256, SMEM_FLOATS * sizeof(float)>>>(
        node_feat, edge_feat,
        W_ih_n, b_ih_n, b_hh_n,
        W_ih_e, b_ih_e, b_hh_e,
        W_nmpn, b_nmpn, W_fc, b_fc, out);
}

// round 12
// speedup vs baseline: 1.0415x; 1.0415x over previous
#include <cuda_runtime.h>

#define NN 200000
#define EE 200000
constexpr int TILE = 16;
constexpr int NTILES = NN / TILE;

__device__ int g_inv[NN];

__global__ void k_init_inv() {
    int i = blockIdx.x * blockDim.x + threadIdx.x;
    if (i < NN) g_inv[i] = -1;
}

__global__ void k_scatter(const int* __restrict__ dst) {
    int e = blockIdx.x * blockDim.x + threadIdx.x;
    if (e < EE) {
        unsigned d = (unsigned)dst[e];
        if (d < NN) g_inv[d] = e;
    }
}

__device__ __forceinline__ float tanh_hw(float x) {
    float y;
    asm("tanh.approx.f32 %0, %1;" : "=f"(y) : "f"(x));
    return y;
}
__device__ __forceinline__ float sigf(float x) {
    return fmaf(tanh_hw(0.5f * x), 0.5f, 0.5f);
}

// ---- shared-memory layout (float offsets, all multiples of 4 for 16B alignment) ----
constexpr int O_WIHE = 0;               // 384*2 edge W (i,g,o rows)
constexpr int O_BE   = O_WIHE + 768;    // 384
constexpr int O_WNM  = O_BE   + 384;    // 21 * 260 (padded stride, 16B-aligned rows)
constexpr int O_BNM  = O_WNM  + 5460;   // 24
constexpr int O_WFC  = O_BNM  + 24;     // 4 * 132
constexpr int O_BFC  = O_WFC  + 528;    // 4
constexpr int O_XN   = O_BFC  + 4;      // 16 * 24 (padded)
constexpr int O_XE   = O_XN   + 384;    // 32
constexpr int O_XN1  = O_XE   + 32;     // 16 * 24
constexpr int O_HN1  = O_XN1  + 384;    // 16 * 132
constexpr int O_MAIL = O_HN1  + 2112;   // 16 * 132
constexpr int O_HN2  = O_MAIL + 2112;   // 16 * 132
constexpr int O_RED  = O_HN2  + 2112;   // 336 * 9 split-K partials
constexpr int O_INV  = O_RED  + 3024;   // 16 ints
constexpr int SMEM_FLOATS = O_INV + 16; // 17344 floats = ~69.4 KB

// node LSTM (zero state) with weights in registers.
// thread = (k = tid&127, half = tid>>7); each thread does 8 nodes at fixed k.
// x loads are float4 broadcasts (stride-24 padded rows).
__device__ __forceinline__ void lstm_n_reg(
    const float* __restrict__ s_x, float* __restrict__ out_h,
    const float* __restrict__ wi, const float* __restrict__ wg, const float* __restrict__ wo,
    float bi, float bg, float bo, int k, int half)
{
    float ai[8], ag[8], ao[8];
#pragma unroll
    for (int m = 0; m < 8; m++) { ai[m] = 0.f; ag[m] = 0.f; ao[m] = 0.f; }
#pragma unroll
    for (int j = 0; j < 20; j += 4) {
#pragma unroll
        for (int m = 0; m < 8; m++) {
            const float4 xv = *reinterpret_cast<const float4*>(s_x + (half + 2 * m) * 24 + j);
            ai[m] = fmaf(xv.x, wi[j],     ai[m]);
            ag[m] = fmaf(xv.x, wg[j],     ag[m]);
            ao[m] = fmaf(xv.x, wo[j],     ao[m]);
            ai[m] = fmaf(xv.y, wi[j + 1], ai[m]);
            ag[m] = fmaf(xv.y, wg[j + 1], ag[m]);
            ao[m] = fmaf(xv.y, wo[j + 1], ao[m]);
            ai[m] = fmaf(xv.z, wi[j + 2], ai[m]);
            ag[m] = fmaf(xv.z, wg[j + 2], ag[m]);
            ao[m] = fmaf(xv.z, wo[j + 2], ao[m]);
            ai[m] = fmaf(xv.w, wi[j + 3], ai[m]);
            ag[m] = fmaf(xv.w, wg[j + 3], ag[m]);
            ao[m] = fmaf(xv.w, wo[j + 3], ao[m]);
        }
    }
#pragma unroll
    for (int m = 0; m < 8; m++) {
        float x = s_x[(half + 2 * m) * 24 + 20];
        ai[m] = fmaf(x, wi[20], ai[m]);
        ag[m] = fmaf(x, wg[20], ag[m]);
        ao[m] = fmaf(x, wo[20], ao[m]);
    }
#pragma unroll
    for (int m = 0; m < 8; m++) {
        int n = half + 2 * m;
        float c = sigf(ai[m] + bi) * tanh_hw(ag[m] + bg);
        float h = sigf(ao[m] + bo) * tanh_hw(c);
        out_h[n * 132 + k] = h;
    }
}

__global__ void __launch_bounds__(256, 2) k_main(
    const float* __restrict__ node_feat,
    const float* __restrict__ edge_feat,
    const float* __restrict__ W_ih_n, const float* __restrict__ b_ih_n, const float* __restrict__ b_hh_n,
    const float* __restrict__ W_ih_e, const float* __restrict__ b_ih_e, const float* __restrict__ b_hh_e,
    const float* __restrict__ W_nmpn, const float* __restrict__ b_nmpn,
    const float* __restrict__ W_fc, const float* __restrict__ b_fc,
    float* __restrict__ out) {
    extern __shared__ float sm[];
    const int tid = threadIdx.x;
    const int k = tid & 127;
    const int half = tid >> 7;

    // ---- node-LSTM weights into registers (constant per thread for whole kernel) ----
    float wi[21], wg[21], wo[21];
#pragma unroll
    for (int j = 0; j < 21; j++) {
        wi[j] = W_ih_n[k * 21 + j];
        wg[j] = W_ih_n[(256 + k) * 21 + j];
        wo[j] = W_ih_n[(384 + k) * 21 + j];
    }
    const float bi = b_ih_n[k]       + b_hh_n[k];
    const float bg = b_ih_n[256 + k] + b_hh_n[256 + k];
    const float bo = b_ih_n[384 + k] + b_hh_n[384 + k];

    // ---- stage small weights into shared ----
    for (int q = tid; q < 384; q += 256) {
        int srow = q < 128 ? q : q + 128;  // skip dead f-gate rows
        sm[O_BE + q] = b_ih_e[srow] + b_hh_e[srow];
        sm[O_WIHE + 2 * q]     = W_ih_e[srow * 2];
        sm[O_WIHE + 2 * q + 1] = W_ih_e[srow * 2 + 1];
    }
    for (int idx = tid; idx < 21 * 256; idx += 256) {
        int c = idx >> 8, j = idx & 255;
        sm[O_WNM + c * 260 + j] = W_nmpn[idx];
    }
    if (tid < 21) sm[O_BNM + tid] = b_nmpn[tid];
    for (int idx = tid; idx < 512; idx += 256) {
        int c = idx >> 7, j = idx & 127;
        sm[O_WFC + c * 132 + j] = W_fc[idx];
    }
    if (tid < 4) sm[O_BFC + tid] = b_fc[tid];
    __syncthreads();

    int* s_inv = (int*)(sm + O_INV);

    for (int tile = blockIdx.x; tile < NTILES; tile += gridDim.x) {
        const int base = tile * TILE;

        // ---- load tile inputs ----
        if (tid < TILE) {
            int e = g_inv[base + tid];
            s_inv[tid] = e;
            float x0 = 0.f, x1 = 0.f;
            if (e >= 0) { x0 = edge_feat[2 * e]; x1 = edge_feat[2 * e + 1]; }
            sm[O_XE + 2 * tid] = x0;
            sm[O_XE + 2 * tid + 1] = x1;
        }
        for (int p = tid; p < TILE * 21; p += 256) {
            int n = p / 21, j = p % 21;
            sm[O_XN + n * 24 + j] = node_feat[base * 21 + p];
        }
        __syncthreads();

        // ---- stage 1: h_n1 = lstm(xn0) ----
        lstm_n_reg(sm + O_XN, sm + O_HN1, wi, wg, wo, bi, bg, bo, k, half);

        // ---- stage 2: mail = scatter(h_e = lstm(xe0)) via dst-inverse ----
        {
            float wi0 = sm[O_WIHE + 2 * k],           wi1 = sm[O_WIHE + 2 * k + 1];
            float wg0 = sm[O_WIHE + 2 * (128 + k)],   wg1 = sm[O_WIHE + 2 * (128 + k) + 1];
            float wo0 = sm[O_WIHE + 2 * (256 + k)],   wo1 = sm[O_WIHE + 2 * (256 + k) + 1];
            float bei = sm[O_BE + k], beg = sm[O_BE + 128 + k], beo = sm[O_BE + 256 + k];
#pragma unroll
            for (int m = 0; m < 8; m++) {
                int n = half + 2 * m;
                float x0 = sm[O_XE + 2 * n], x1 = sm[O_XE + 2 * n + 1];
                float gi = fmaf(x1, wi1, fmaf(x0, wi0, bei));
                float gg = fmaf(x1, wg1, fmaf(x0, wg0, beg));
                float go = fmaf(x1, wo1, fmaf(x0, wo0, beo));
                float c = sigf(gi) * tanh_hw(gg);
                float h = sigf(go) * tanh_hw(c);
                sm[O_MAIL + n * 132 + k] = (s_inv[n] >= 0) ? h : 0.f;
            }
        }
        __syncthreads();

        // ---- stage 3a: split-K register-blocked message MLP partials ----
        // 96 threads: warp = c-group (7 cols), lane = (ng: 4 nodes, ks: 32-j slice)
        if (tid < 96) {
            const int cg = tid >> 5;
            const int l  = tid & 31;
            const int ng = l >> 3;
            const int ks = l & 7;
            const int n0 = ng * 4;
            const float* dbase = sm + ((ks < 4) ? O_MAIL : O_HN1) + (ks & 3) * 32;
            const float* wbase = sm + O_WNM + cg * 7 * 260 + ks * 32;
            float acc[28];
#pragma unroll
            for (int u = 0; u < 28; u++) acc[u] = 0.f;
#pragma unroll
            for (int it = 0; it < 8; it++) {
                float4 dv[4];
#pragma unroll
                for (int ni = 0; ni < 4; ni++)
                    dv[ni] = *reinterpret_cast<const float4*>(dbase + (n0 + ni) * 132 + it * 4);
#pragma unroll
                for (int ci = 0; ci < 7; ci++) {
                    float4 wv = *reinterpret_cast<const float4*>(wbase + ci * 260 + it * 4);
#pragma unroll
                    for (int ni = 0; ni < 4; ni++) {
                        float a = acc[ci * 4 + ni];
                        a = fmaf(dv[ni].x, wv.x, a);
                        a = fmaf(dv[ni].y, wv.y, a);
                        a = fmaf(dv[ni].z, wv.z, a);
                        a = fmaf(dv[ni].w, wv.w, a);
                        acc[ci * 4 + ni] = a;
                    }
                }
            }
            const int ogbase = (cg * 4 + ng) * 28;
#pragma unroll
            for (int u = 0; u < 28; u++)
                sm[O_RED + (ogbase + u) * 9 + ks] = acc[u];
        }
        __syncthreads();

        // ---- stage 3b: reduce split-K partials, bias + sigmoid -> xn1 ----
        for (int og = tid; og < 336; og += 256) {
            float s = 0.f;
#pragma unroll
            for (int q = 0; q < 8; q++) s += sm[O_RED + og * 9 + q];
            int cg = og / 112, r = og % 112;
            int ng = r / 28,  r2 = r % 28;
            int ci = r2 >> 2, ni = r2 & 3;
            int n = ng * 4 + ni, c = cg * 7 + ci;
            sm[O_XN1 + n * 24 + c] = sigf(s + sm[O_BNM + c]);
        }
        __syncthreads();

        // ---- stage 4: h_n2 = lstm(xn1) ----
        lstm_n_reg(sm + O_XN1, sm + O_HN2, wi, wg, wo, bi, bg, bo, k, half);
        __syncthreads();

        // ---- stage 5: logits + log_softmax ----
        if (tid < 64) {
            int n = tid >> 2, cls = tid & 3;
            const float* w = sm + O_WFC + cls * 132;
            const float* h = sm + O_HN2 + n * 132;
            float acc = sm[O_BFC + cls];
#pragma unroll
            for (int j = 0; j < 128; j += 4) {
                float4 hv = *reinterpret_cast<const float4*>(h + j);
                float4 wv = *reinterpret_cast<const float4*>(w + j);
                acc = fmaf(hv.x, wv.x, acc);
                acc = fmaf(hv.y, wv.y, acc);
                acc = fmaf(hv.z, wv.z, acc);
                acc = fmaf(hv.w, wv.w, acc);
            }
            float mx = acc;
            mx = fmaxf(mx, __shfl_xor_sync(0xFFFFFFFF, mx, 1));
            mx = fmaxf(mx, __shfl_xor_sync(0xFFFFFFFF, mx, 2));
            float ev = __expf(acc - mx);
            float s = ev;
            s += __shfl_xor_sync(0xFFFFFFFF, s, 1);
            s += __shfl_xor_sync(0xFFFFFFFF, s, 2);
            out[(base + n) * 4 + cls] = acc - mx - __logf(s);
        }
        __syncthreads();
    }
}

extern "C" void kernel_launch(void* const* d_in, const int* in_sizes, int n_in,
                              void* d_out, int out_size) {
    const float* node_feat = (const float*)d_in[0];
    const float* edge_feat = (const float*)d_in[1];
    const int*   dst       = (const int*)d_in[3];
    const float* W_ih_n    = (const float*)d_in[4];
    const float* b_ih_n    = (const float*)d_in[6];
    const float* b_hh_n    = (const float*)d_in[7];
    const float* W_ih_e    = (const float*)d_in[8];
    const float* b_ih_e    = (const float*)d_in[10];
    const float* b_hh_e    = (const float*)d_in[11];
    const float* W_nmpn    = (const float*)d_in[12];
    const float* b_nmpn    = (const float*)d_in[13];
    const float* W_fc      = (const float*)d_in[16];
    const float* b_fc      = (const float*)d_in[17];
    float* out = (float*)d_out;

    cudaFuncSetAttribute(k_main, cudaFuncAttributeMaxDynamicSharedMemorySize,
                         SMEM_FLOATS * (int)sizeof(float));

    k_init_inv<<<(NN + 255) / 256, 256>>>();
    k_scatter<<<(EE + 255) / 256, 256>>>(dst);
    // GB300: 152 SMs x 2 blocks/SM = 304 for a single full wave
    k_main<<<304, 256, SMEM_FLOATS * sizeof(float)>>>(
        node_feat, edge_feat,
        W_ih_n, b_ih_n, b_hh_n,
        W_ih_e, b_ih_e, b_hh_e,
        W_nmpn, b_nmpn, W_fc, b_fc, out);
}